// round 5
// baseline (speedup 1.0000x reference)
#include <cuda_runtime.h>
#include <stdint.h>

// z[e, :] = h[src[e], :] * h[dst[e], :]
// h: [N=50000, D=64] fp32 (12.8 MB, L2-resident), src/dst: [E=800000] int32,
// out: [E, 64] fp32.
// R4 was L1tex-top (73%) but issue=18% -> latency-limited on random gathers.
// R5: 8 threads/edge (keeps full-line coalescing) x 2 edges/thread (e, e+E/2)
// -> 8 outstanding gather LDG.128 per thread, half the threads/issue slots.
// __stcs keeps the output stream from evicting h out of L2.

static constexpr int D = 64;
static constexpr int VEC_PER_ROW = D / 4;   // 16 float4 per row

__global__ void __launch_bounds__(256, 8) u_mul_v_kernel(
    const float4* __restrict__ h,        // [N, 16] as float4
    const int* __restrict__ src,         // [E] int32
    const int* __restrict__ dst,         // [E] int32
    float4* __restrict__ out,            // [E, 16] as float4
    int n_edges,
    int half)                            // ceil(E/2)
{
    const int t = blockIdx.x * 256 + threadIdx.x;
    const int p = t >> 3;                // pair id
    const int j = t & 7;                 // float4 slot within row half
    if (p >= half) return;

    const int e0 = p;
    const int e1 = p + half;
    const bool has_e1 = (e1 < n_edges);

    // 8 adjacent threads share each index -> L1 broadcast.
    const int s0 = __ldg(&src[e0]);
    const int d0 = __ldg(&dst[e0]);
    const int s1 = has_e1 ? __ldg(&src[e1]) : 0;
    const int d1 = has_e1 ? __ldg(&dst[e1]) : 0;

    const float4* __restrict__ hs0 = h + (size_t)s0 * VEC_PER_ROW;
    const float4* __restrict__ hd0 = h + (size_t)d0 * VEC_PER_ROW;
    const float4* __restrict__ hs1 = h + (size_t)s1 * VEC_PER_ROW;
    const float4* __restrict__ hd1 = h + (size_t)d1 * VEC_PER_ROW;

    // Issue all 8 gathers up front for maximum MLP.
    const float4 a0 = __ldg(hs0 + j);
    const float4 b0 = __ldg(hd0 + j);
    const float4 a1 = __ldg(hs0 + j + 8);
    const float4 b1 = __ldg(hd0 + j + 8);
    const float4 c0 = __ldg(hs1 + j);
    const float4 e0v = __ldg(hd1 + j);
    const float4 c1 = __ldg(hs1 + j + 8);
    const float4 e1v = __ldg(hd1 + j + 8);

    float4 r0, r1;
    r0.x = a0.x * b0.x; r0.y = a0.y * b0.y;
    r0.z = a0.z * b0.z; r0.w = a0.w * b0.w;
    r1.x = a1.x * b1.x; r1.y = a1.y * b1.y;
    r1.z = a1.z * b1.z; r1.w = a1.w * b1.w;

    float4* o0 = out + (size_t)e0 * VEC_PER_ROW + j;
    __stcs(o0, r0);
    __stcs(o0 + 8, r1);

    if (has_e1) {
        float4 q0, q1;
        q0.x = c0.x * e0v.x; q0.y = c0.y * e0v.y;
        q0.z = c0.z * e0v.z; q0.w = c0.w * e0v.w;
        q1.x = c1.x * e1v.x; q1.y = c1.y * e1v.y;
        q1.z = c1.z * e1v.z; q1.w = c1.w * e1v.w;

        float4* o1 = out + (size_t)e1 * VEC_PER_ROW + j;
        __stcs(o1, q0);
        __stcs(o1 + 8, q1);
    }
}

extern "C" void kernel_launch(void* const* d_in, const int* in_sizes, int n_in,
                              void* d_out, int out_size) {
    const float4* h = (const float4*)d_in[0];
    const int* src = (const int*)d_in[1];
    const int* dst = (const int*)d_in[2];
    float4* out = (float4*)d_out;

    const int n_edges = in_sizes[1];          // E = 800000
    const int half = (n_edges + 1) / 2;       // 400000
    const long long total = (long long)half * 8;
    const int threads = 256;
    const int blocks = (int)((total + threads - 1) / threads);

    u_mul_v_kernel<<<blocks, threads>>>(h, src, dst, out, n_edges, half);
}